// round 5
// baseline (speedup 1.0000x reference)
#include <cuda_runtime.h>
#include <cstdint>

typedef unsigned long long u64;
typedef unsigned int u32;

#define NROWS 1024
#define NCOLS 16384
#define NTOT (NROWS*NCOLS)
#define CAP 16384
#define HBINS 256
#define HLO 2.0f
#define HSCALE 64.0f
#define TARGET 12000u
#define MAXCUM 16000u

// device-global scratch (no allocations allowed)
__device__ u32 g_hist[HBINS];
__device__ float g_thr;
__device__ u32 g_count;
__device__ u32 g_overflow;
__device__ u64 g_keys[CAP];

__global__ void k_init() {
    int t = blockIdx.x * blockDim.x + threadIdx.x;
    int stride = gridDim.x * blockDim.x;
    for (int i = t; i < CAP; i += stride) g_keys[i] = 0ull;
    if (t < HBINS) g_hist[t] = 0;
    if (t == 0) { g_count = 0; g_overflow = 0; }
}

__global__ void k_hist(const float4* __restrict__ c4) {
    __shared__ u32 sh[HBINS];
    for (int i = threadIdx.x; i < HBINS; i += blockDim.x) sh[i] = 0;
    __syncthreads();
    int stride = gridDim.x * blockDim.x;
    for (int i = blockIdx.x * blockDim.x + threadIdx.x; i < NTOT / 4; i += stride) {
        float4 v = c4[i];
        float a0 = v.x, a1 = v.y, a2 = v.z, a3 = v.w;
        if (a0 >= HLO) { int b = (int)((a0 - HLO) * HSCALE); if (b > HBINS-1) b = HBINS-1; atomicAdd(&sh[b], 1u); }
        if (a1 >= HLO) { int b = (int)((a1 - HLO) * HSCALE); if (b > HBINS-1) b = HBINS-1; atomicAdd(&sh[b], 1u); }
        if (a2 >= HLO) { int b = (int)((a2 - HLO) * HSCALE); if (b > HBINS-1) b = HBINS-1; atomicAdd(&sh[b], 1u); }
        if (a3 >= HLO) { int b = (int)((a3 - HLO) * HSCALE); if (b > HBINS-1) b = HBINS-1; atomicAdd(&sh[b], 1u); }
    }
    __syncthreads();
    for (int i = threadIdx.x; i < HBINS; i += blockDim.x)
        if (sh[i]) atomicAdd(&g_hist[i], sh[i]);
}

__global__ void k_thresh() {
    u32 cum = 0;
    int chosen = HBINS;   // degenerate: thr=6.0 -> ~0 candidates -> exact fallback path
    for (int b = HBINS - 1; b >= 0; b--) {
        u32 h = g_hist[b];
        if (cum + h > MAXCUM) break;
        cum += h;
        chosen = b;
        if (cum >= TARGET) break;
    }
    g_thr = HLO + (float)chosen * (1.0f / HSCALE);
}

__global__ void k_compact(const float4* __restrict__ c4) {
    float thr = g_thr;
    int stride = gridDim.x * blockDim.x;
    for (int i = blockIdx.x * blockDim.x + threadIdx.x; i < NTOT / 4; i += stride) {
        float4 v = c4[i];
        float a[4] = { v.x, v.y, v.z, v.w };
        #pragma unroll
        for (int k = 0; k < 4; k++) {
            if (a[k] >= thr) {
                u32 pos = atomicAdd(&g_count, 1u);
                u32 flat = (u32)(i * 4 + k);
                if (pos < CAP) {
                    u32 enc = __float_as_uint(a[k]);   // all candidates > 0: raw bits order-preserving
                    g_keys[pos] = ((u64)enc << 24) | (u64)(0xFFFFFFu - flat);
                } else {
                    g_overflow = 1;
                }
            }
        }
    }
}

// k_final: static shared only (<48KB). Sort runs in global memory (g_keys).
__global__ void __launch_bounds__(1024, 1)
k_final(const float* __restrict__ cost, float* __restrict__ out, int out_size) {
    __shared__ unsigned char colUsed[NCOLS];
    __shared__ unsigned char rowUsed[NROWS];
    __shared__ unsigned short colOf[NROWS];
    __shared__ u64 redBuf[32];
    __shared__ int scnt_s;

    int tid = threadIdx.x;
    u32 M = g_count; if (M > CAP) M = CAP;
    if (g_overflow) M = 0;   // pathological: pure-fallback path (exact, slow)

    for (int i = tid; i < NCOLS; i += 1024) colUsed[i] = 0;
    for (int i = tid; i < NROWS; i += 1024) { rowUsed[i] = 0; colOf[i] = 0; }
    if (tid == 0) scnt_s = 0;
    __syncthreads();

    // ---- bitonic sort in GLOBAL memory, descending (zero pad sinks to end) ----
    for (int k = 2; k <= CAP; k <<= 1) {
        for (int j = k >> 1; j > 0; j >>= 1) {
            for (int i = tid; i < CAP; i += 1024) {
                int p = i ^ j;
                if (p > i) {
                    u64 a = g_keys[i], b = g_keys[p];
                    bool desc = ((i & k) == 0);
                    if (desc ? (a < b) : (a > b)) { g_keys[i] = b; g_keys[p] = a; }
                }
            }
            __syncthreads();
        }
    }

    // ---- warp-windowed greedy scan (warp 0 only) ----
    if (tid < 32) {
        int lane = tid;
        int assigned = 0;
        for (int base = 0; base < (int)M && assigned < NROWS; base += 32) {
            __syncwarp();
            u64 key = g_keys[base + lane];
            int flat = 0xFFFFFF - (int)(key & 0xFFFFFFu);
            int r = flat >> 14;
            int c = flat & 0x3FFF;
            bool valid = (key != 0ull) && (rowUsed[r] == 0) && (colUsed[c] == 0);
            u32 mask = __ballot_sync(0xFFFFFFFFu, valid);
            while (mask && assigned < NROWS) {
                int leader = __ffs(mask) - 1;
                int lflat = __shfl_sync(0xFFFFFFFFu, flat, leader);
                int lr = lflat >> 14, lc = lflat & 0x3FFF;
                if (lane == leader) {
                    rowUsed[lr] = 1; colUsed[lc] = 1;
                    colOf[lr] = (unsigned short)lc;
                }
                assigned++;
                if (valid && (r == lr || c == lc)) valid = false;
                mask = __ballot_sync(0xFFFFFFFFu, valid);
            }
        }
        if (lane == 0) scnt_s = assigned;
    }

    // ---- exact fallback: iterative masked global argmax for any rows not
    //      assignable from the candidate set ----
    while (true) {
        __syncthreads();
        if (scnt_s >= NROWS) break;
        u64 best = 0;
        for (int i = tid; i < NTOT; i += 1024) {
            int r = i >> 14;
            if (rowUsed[r]) continue;
            int c = i & 0x3FFF;
            if (colUsed[c]) continue;
            float v = cost[i];
            u32 u = __float_as_uint(v);
            u32 enc = (u & 0x80000000u) ? ~u : (u | 0x80000000u);
            u64 kk = ((u64)enc << 24) | (u64)(0xFFFFFFu - (u32)i);
            if (kk > best) best = kk;
        }
        #pragma unroll
        for (int o = 16; o > 0; o >>= 1) {
            u64 t2 = __shfl_down_sync(0xFFFFFFFFu, best, o);
            if (t2 > best) best = t2;
        }
        if ((tid & 31) == 0) redBuf[tid >> 5] = best;
        __syncthreads();
        if (tid < 32) {
            u64 b = redBuf[tid];
            #pragma unroll
            for (int o = 16; o > 0; o >>= 1) {
                u64 t2 = __shfl_down_sync(0xFFFFFFFFu, b, o);
                if (t2 > b) b = t2;
            }
            if (tid == 0) {
                int flat = 0xFFFFFF - (int)(b & 0xFFFFFFu);
                int r = flat >> 14, c = flat & 0x3FFF;
                rowUsed[r] = 1; colUsed[c] = 1;
                colOf[r] = (unsigned short)c;
                scnt_s = scnt_s + 1;
            }
        }
        __syncthreads();
    }

    // ---- write output as FLOAT32: rows (sorted => arange) then cols ----
    // (indices <= 16383 are exactly representable in fp32)
    if (out_size >= 2 * NROWS) {
        for (int i = tid; i < NROWS; i += 1024) {
            out[i] = (float)i;
            out[NROWS + i] = (float)colOf[i];
        }
    } else {
        for (int i = tid; i < NROWS && i < out_size; i += 1024)
            out[i] = (float)colOf[i];
    }
}

extern "C" void kernel_launch(void* const* d_in, const int* in_sizes, int n_in,
                              void* d_out, int out_size) {
    const float* cost = (const float*)d_in[0];
    float* out = (float*)d_out;
    (void)in_sizes; (void)n_in;

    k_init<<<64, 256>>>();
    k_hist<<<1024, 256>>>((const float4*)cost);
    k_thresh<<<1, 1>>>();
    k_compact<<<1024, 256>>>((const float4*)cost);
    k_final<<<1, 1024>>>(cost, out, out_size);
}

// round 6
// speedup vs baseline: 2.5277x; 2.5277x over previous
#include <cuda_runtime.h>
#include <cstdint>

typedef unsigned long long u64;
typedef unsigned int u32;

#define NROWS 1024
#define NCOLS 16384
#define NTOT (NROWS*NCOLS)
#define CAP 16384
#define FBINS 4096
#define HLO 2.0f
#define HSCALE 1024.0f
#define MAXCUM 16000u

#define SGRID 2048
#define SBLK 256
#define SSTRIDE (SGRID*SBLK)   // 524288; NTOT/4 = 4194304 = 8*SSTRIDE exactly

// device-global scratch (no allocations allowed)
__device__ u32 g_hist[FBINS];
__device__ u32 g_bincnt[FBINS];
__device__ u32 g_binoff[FBINS];
__device__ u32 g_chosen;
__device__ u32 g_total;
__device__ u32 g_overflow;
__device__ u64 g_keys[CAP];

__global__ void k_init() {
    int t = blockIdx.x * blockDim.x + threadIdx.x;
    int stride = gridDim.x * blockDim.x;
    for (int i = t; i < FBINS; i += stride) { g_hist[i] = 0; g_bincnt[i] = 0; }
    if (t == 0) { g_chosen = FBINS; g_total = 0; g_overflow = 0; }
}

__device__ __forceinline__ int binof(float v) {
    int b = (int)((v - HLO) * HSCALE);
    return (b > FBINS - 1) ? (FBINS - 1) : b;
}

__global__ void __launch_bounds__(SBLK)
k_hist(const float4* __restrict__ c4) {
    __shared__ u32 sh[FBINS];
    for (int i = threadIdx.x; i < FBINS; i += SBLK) sh[i] = 0;
    __syncthreads();
    int idx = blockIdx.x * SBLK + threadIdx.x;
    #pragma unroll
    for (int k = 0; k < 8; k++) {
        float4 v = c4[idx + k * SSTRIDE];
        if (v.x >= HLO) atomicAdd(&sh[binof(v.x)], 1u);
        if (v.y >= HLO) atomicAdd(&sh[binof(v.y)], 1u);
        if (v.z >= HLO) atomicAdd(&sh[binof(v.z)], 1u);
        if (v.w >= HLO) atomicAdd(&sh[binof(v.w)], 1u);
    }
    __syncthreads();
    for (int i = threadIdx.x; i < FBINS; i += SBLK)
        if (sh[i]) atomicAdd(&g_hist[i], sh[i]);
}

// one block: suffix-sum histogram, pick threshold bin, write per-bin offsets
__global__ void __launch_bounds__(1024)
k_scan() {
    __shared__ u32 s[1024];
    __shared__ u32 chosen_s;
    int tid = threadIdx.x;
    if (tid == 0) chosen_s = FBINS;

    // reversed positions r = tid*4+q  ->  bin b = FBINS-1-r
    u32 x[4], pre[4];
    u32 run = 0;
    #pragma unroll
    for (int q = 0; q < 4; q++) {
        int b = FBINS - 1 - (tid * 4 + q);
        x[q] = g_hist[b];
        pre[q] = run;          // exclusive within thread
        run += x[q];
    }
    s[tid] = run;
    __syncthreads();
    for (int off = 1; off < 1024; off <<= 1) {
        u32 t = (tid >= off) ? s[tid - off] : 0;
        __syncthreads();
        s[tid] += t;
        __syncthreads();
    }
    u32 excl = (tid > 0) ? s[tid - 1] : 0;

    #pragma unroll
    for (int q = 0; q < 4; q++) {
        int b = FBINS - 1 - (tid * 4 + q);
        u32 S = excl + pre[q] + x[q];      // inclusive suffix sum for bin b
        g_binoff[b] = S - x[q];            // descending-concat start of bin b
        if (S <= MAXCUM) atomicMin(&chosen_s, (u32)b);
    }
    __syncthreads();
    if (tid == 0) {
        u32 ch = chosen_s;
        g_chosen = ch;
        g_total = (ch < FBINS) ? (g_binoff[ch] + g_hist[ch]) : 0;
    }
}

__global__ void __launch_bounds__(SBLK)
k_compact(const float4* __restrict__ c4) {
    u32 chosen = g_chosen;
    int idx = blockIdx.x * SBLK + threadIdx.x;
    #pragma unroll
    for (int k = 0; k < 8; k++) {
        int i = idx + k * SSTRIDE;
        float4 v = c4[i];
        float a[4] = { v.x, v.y, v.z, v.w };
        #pragma unroll
        for (int q = 0; q < 4; q++) {
            if (a[q] >= HLO) {
                int b = binof(a[q]);
                if ((u32)b >= chosen) {
                    u32 pos = g_binoff[b] + atomicAdd(&g_bincnt[b], 1u);
                    u32 flat = (u32)(i * 4 + q);
                    if (pos < CAP) {
                        u32 enc = __float_as_uint(a[q]);  // candidates > 0: raw bits order-preserving
                        g_keys[pos] = ((u64)enc << 24) | (u64)(0xFFFFFFu - flat);
                    } else {
                        g_overflow = 1;
                    }
                }
            }
        }
    }
}

// one block per bin: tiny smem bitonic (bins are ~45 elements)
__global__ void __launch_bounds__(128)
k_sortbins() {
    int b = blockIdx.x;
    u32 chosen = g_chosen;
    if ((u32)b < chosen) return;
    u32 cnt = g_bincnt[b];
    if (cnt <= 1) return;
    if (cnt > 1024) { g_overflow = 1; return; }
    __shared__ u64 sk[1024];
    u32 off = g_binoff[b];
    u32 m = 2; while (m < cnt) m <<= 1;
    int tid = threadIdx.x;
    for (u32 i = tid; i < m; i += 128) sk[i] = (i < cnt) ? g_keys[off + i] : 0ull;
    __syncthreads();
    for (u32 k = 2; k <= m; k <<= 1) {
        for (u32 j = k >> 1; j > 0; j >>= 1) {
            for (u32 i = tid; i < m; i += 128) {
                u32 p = i ^ j;
                if (p > i) {
                    u64 a = sk[i], bb = sk[p];
                    bool desc = ((i & k) == 0);
                    if (desc ? (a < bb) : (a > bb)) { sk[i] = bb; sk[p] = a; }
                }
            }
            __syncthreads();
        }
    }
    for (u32 i = tid; i < cnt; i += 128) g_keys[off + i] = sk[i];
}

// greedy scan over globally-descending keys + exact fallback + output
__global__ void __launch_bounds__(1024, 1)
k_final(const float* __restrict__ cost, float* __restrict__ out, int out_size) {
    __shared__ unsigned char colUsed[NCOLS];
    __shared__ unsigned char rowUsed[NROWS];
    __shared__ unsigned short colOf[NROWS];
    __shared__ u64 redBuf[32];
    __shared__ int scnt_s;

    int tid = threadIdx.x;
    u32 total = g_total;
    if (g_overflow) total = 0;   // pathological: pure-fallback path (exact)

    for (int i = tid; i < NCOLS; i += 1024) colUsed[i] = 0;
    for (int i = tid; i < NROWS; i += 1024) { rowUsed[i] = 0; colOf[i] = 0; }
    if (tid == 0) scnt_s = 0;
    __syncthreads();

    // ---- warp-windowed greedy scan (warp 0), prefetching next window ----
    if (tid < 32) {
        int lane = tid;
        int assigned = 0;
        u64 key = (lane < (int)total) ? g_keys[lane] : 0ull;
        for (int base = 0; base < (int)total && assigned < NROWS; base += 32) {
            int nxt = base + 32 + lane;
            u64 key_next = (nxt < (int)total) ? __ldg(&g_keys[nxt]) : 0ull;

            int flat = 0xFFFFFF - (int)(key & 0xFFFFFFu);
            int r = flat >> 14;
            int c = flat & 0x3FFF;
            bool valid = (key != 0ull) && (rowUsed[r] == 0) && (colUsed[c] == 0);
            u32 mask = __ballot_sync(0xFFFFFFFFu, valid);
            while (mask && assigned < NROWS) {
                int leader = __ffs(mask) - 1;
                int lflat = __shfl_sync(0xFFFFFFFFu, flat, leader);
                int lr = lflat >> 14, lc = lflat & 0x3FFF;
                if (lane == leader) {
                    rowUsed[lr] = 1; colUsed[lc] = 1;
                    colOf[lr] = (unsigned short)lc;
                }
                assigned++;
                if (valid && (r == lr || c == lc)) valid = false;
                mask = __ballot_sync(0xFFFFFFFFu, valid);
            }
            key = key_next;
        }
        if (lane == 0) scnt_s = assigned;
    }

    // ---- exact fallback: masked global argmax for any unassigned rows ----
    while (true) {
        __syncthreads();
        if (scnt_s >= NROWS) break;
        u64 best = 0;
        for (int i = tid; i < NTOT; i += 1024) {
            int r = i >> 14;
            if (rowUsed[r]) continue;
            int c = i & 0x3FFF;
            if (colUsed[c]) continue;
            float v = cost[i];
            u32 u = __float_as_uint(v);
            u32 enc = (u & 0x80000000u) ? ~u : (u | 0x80000000u);
            u64 kk = ((u64)enc << 24) | (u64)(0xFFFFFFu - (u32)i);
            if (kk > best) best = kk;
        }
        #pragma unroll
        for (int o = 16; o > 0; o >>= 1) {
            u64 t2 = __shfl_down_sync(0xFFFFFFFFu, best, o);
            if (t2 > best) best = t2;
        }
        if ((tid & 31) == 0) redBuf[tid >> 5] = best;
        __syncthreads();
        if (tid < 32) {
            u64 b = redBuf[tid];
            #pragma unroll
            for (int o = 16; o > 0; o >>= 1) {
                u64 t2 = __shfl_down_sync(0xFFFFFFFFu, b, o);
                if (t2 > b) b = t2;
            }
            if (tid == 0) {
                int flat = 0xFFFFFF - (int)(b & 0xFFFFFFu);
                int r = flat >> 14, c = flat & 0x3FFF;
                rowUsed[r] = 1; colUsed[c] = 1;
                colOf[r] = (unsigned short)c;
                scnt_s = scnt_s + 1;
            }
        }
        __syncthreads();
    }

    // ---- write output as float32: rows (arange) then cols ----
    if (out_size >= 2 * NROWS) {
        for (int i = tid; i < NROWS; i += 1024) {
            out[i] = (float)i;
            out[NROWS + i] = (float)colOf[i];
        }
    } else {
        for (int i = tid; i < NROWS && i < out_size; i += 1024)
            out[i] = (float)colOf[i];
    }
}

extern "C" void kernel_launch(void* const* d_in, const int* in_sizes, int n_in,
                              void* d_out, int out_size) {
    const float* cost = (const float*)d_in[0];
    float* out = (float*)d_out;
    (void)in_sizes; (void)n_in;

    k_init<<<8, 1024>>>();
    k_hist<<<SGRID, SBLK>>>((const float4*)cost);
    k_scan<<<1, 1024>>>();
    k_compact<<<SGRID, SBLK>>>((const float4*)cost);
    k_sortbins<<<FBINS, 128>>>();
    k_final<<<1, 1024>>>(cost, out, out_size);
}

// round 7
// speedup vs baseline: 2.9595x; 1.1708x over previous
#include <cuda_runtime.h>
#include <cstdint>

typedef unsigned long long u64;
typedef unsigned int u32;

#define NROWS 1024
#define NCOLS 16384
#define NTOT (NROWS*NCOLS)
#define CAP 16384
#define FBINS 4096
#define HLO 2.0f
#define HSCALE 1024.0f
#define MAXCUM 16000u

#define SGRID 2048
#define SBLK 256
#define SSTRIDE (SGRID*SBLK)   // 524288; NTOT/4 = 4194304 = 8*SSTRIDE exactly

// device-global scratch (no allocations allowed)
__device__ u32 g_hist[FBINS];
__device__ u32 g_bincnt[FBINS];
__device__ u32 g_binoff[FBINS];
__device__ u32 g_chosen;
__device__ u32 g_total;
__device__ u32 g_overflow;
__device__ u64 g_keys[CAP];

__global__ void k_init() {
    int t = blockIdx.x * blockDim.x + threadIdx.x;
    int stride = gridDim.x * blockDim.x;
    for (int i = t; i < FBINS; i += stride) { g_hist[i] = 0; g_bincnt[i] = 0; }
    if (t == 0) { g_chosen = FBINS; g_total = 0; g_overflow = 0; }
}

__device__ __forceinline__ int binof(float v) {
    int b = (int)((v - HLO) * HSCALE);
    return (b > FBINS - 1) ? (FBINS - 1) : b;
}

__global__ void __launch_bounds__(SBLK)
k_hist(const float4* __restrict__ c4) {
    __shared__ u32 sh[FBINS];
    for (int i = threadIdx.x; i < FBINS; i += SBLK) sh[i] = 0;
    __syncthreads();
    int idx = blockIdx.x * SBLK + threadIdx.x;
    float4 vv[8];
    #pragma unroll
    for (int k = 0; k < 8; k++) vv[k] = c4[idx + k * SSTRIDE];   // front-batched: MLP=8
    #pragma unroll
    for (int k = 0; k < 8; k++) {
        float4 v = vv[k];
        if (v.x >= HLO) atomicAdd(&sh[binof(v.x)], 1u);
        if (v.y >= HLO) atomicAdd(&sh[binof(v.y)], 1u);
        if (v.z >= HLO) atomicAdd(&sh[binof(v.z)], 1u);
        if (v.w >= HLO) atomicAdd(&sh[binof(v.w)], 1u);
    }
    __syncthreads();
    for (int i = threadIdx.x; i < FBINS; i += SBLK)
        if (sh[i]) atomicAdd(&g_hist[i], sh[i]);
}

// one block: suffix-sum histogram, pick threshold bin, write per-bin offsets
__global__ void __launch_bounds__(1024)
k_scan() {
    __shared__ u32 s[1024];
    __shared__ u32 chosen_s;
    int tid = threadIdx.x;
    if (tid == 0) chosen_s = FBINS;

    u32 x[4], pre[4];
    u32 run = 0;
    #pragma unroll
    for (int q = 0; q < 4; q++) {
        int b = FBINS - 1 - (tid * 4 + q);
        x[q] = g_hist[b];
        pre[q] = run;
        run += x[q];
    }
    s[tid] = run;
    __syncthreads();
    for (int off = 1; off < 1024; off <<= 1) {
        u32 t = (tid >= off) ? s[tid - off] : 0;
        __syncthreads();
        s[tid] += t;
        __syncthreads();
    }
    u32 excl = (tid > 0) ? s[tid - 1] : 0;

    #pragma unroll
    for (int q = 0; q < 4; q++) {
        int b = FBINS - 1 - (tid * 4 + q);
        u32 S = excl + pre[q] + x[q];      // inclusive suffix sum for bin b
        g_binoff[b] = S - x[q];
        if (S <= MAXCUM) atomicMin(&chosen_s, (u32)b);
    }
    __syncthreads();
    if (tid == 0) {
        u32 ch = chosen_s;
        g_chosen = ch;
        g_total = (ch < FBINS) ? (g_binoff[ch] + g_hist[ch]) : 0;
    }
}

__global__ void __launch_bounds__(SBLK)
k_compact(const float4* __restrict__ c4) {
    u32 chosen = g_chosen;
    int idx = blockIdx.x * SBLK + threadIdx.x;
    float4 vv[8];
    #pragma unroll
    for (int k = 0; k < 8; k++) vv[k] = c4[idx + k * SSTRIDE];   // front-batched: MLP=8
    #pragma unroll
    for (int k = 0; k < 8; k++) {
        int i = idx + k * SSTRIDE;
        float a[4] = { vv[k].x, vv[k].y, vv[k].z, vv[k].w };
        #pragma unroll
        for (int q = 0; q < 4; q++) {
            if (a[q] >= HLO) {
                int b = binof(a[q]);
                if ((u32)b >= chosen) {
                    u32 pos = g_binoff[b] + atomicAdd(&g_bincnt[b], 1u);
                    u32 flat = (u32)(i * 4 + q);
                    if (pos < CAP) {
                        u32 enc = __float_as_uint(a[q]);  // candidates > 0: raw bits order-preserving
                        g_keys[pos] = ((u64)enc << 24) | (u64)(0xFFFFFFu - flat);
                    } else {
                        g_overflow = 1;
                    }
                }
            }
        }
    }
}

// one block per bin: tiny smem bitonic (bins are ~40-70 elements)
__global__ void __launch_bounds__(128)
k_sortbins() {
    int b = blockIdx.x;
    u32 chosen = g_chosen;
    if ((u32)b < chosen) return;
    u32 cnt = g_bincnt[b];
    if (cnt <= 1) return;
    if (cnt > 1024) { g_overflow = 1; return; }
    __shared__ u64 sk[1024];
    u32 off = g_binoff[b];
    u32 m = 2; while (m < cnt) m <<= 1;
    int tid = threadIdx.x;
    for (u32 i = tid; i < m; i += 128) sk[i] = (i < cnt) ? g_keys[off + i] : 0ull;
    __syncthreads();
    for (u32 k = 2; k <= m; k <<= 1) {
        for (u32 j = k >> 1; j > 0; j >>= 1) {
            for (u32 i = tid; i < m; i += 128) {
                u32 p = i ^ j;
                if (p > i) {
                    u64 a = sk[i], bb = sk[p];
                    bool desc = ((i & k) == 0);
                    if (desc ? (a < bb) : (a > bb)) { sk[i] = bb; sk[p] = a; }
                }
            }
            __syncthreads();
        }
    }
    for (u32 i = tid; i < cnt; i += 128) g_keys[off + i] = sk[i];
}

// greedy scan over globally-descending keys + exact fallback + output
__global__ void __launch_bounds__(1024, 1)
k_final(const float* __restrict__ cost, float* __restrict__ out, int out_size) {
    __shared__ unsigned char colUsed[NCOLS];
    __shared__ unsigned char rowUsed[NROWS];
    __shared__ unsigned short colOf[NROWS];
    __shared__ u64 redBuf[32];
    __shared__ int scnt_s;

    int tid = threadIdx.x;
    u32 total = g_total;
    if (g_overflow) total = 0;   // pathological: pure-fallback path (exact)

    for (int i = tid; i < NCOLS; i += 1024) colUsed[i] = 0;
    for (int i = tid; i < NROWS; i += 1024) { rowUsed[i] = 0; colOf[i] = 0; }
    if (tid == 0) scnt_s = 0;
    __syncthreads();

    // ---- warp-windowed greedy scan (warp 0), match-based parallel acceptance ----
    //
    // Per window of 32 sorted candidates:
    //   valid    = key nonzero && row free && col free (pre-window state)
    //   accept0  = valid && no row/col match with any EARLIER valid lane.
    //     * accept0 lanes are exactly greedy-accepted: nothing before them
    //       (pre-window or in-window) uses their row/col. They are pairwise
    //       row/col-distinct, so they commit in parallel.
    //   quest    = valid && conflicts with an earlier valid lane. Rare
    //     (~C(32,2)*(1/1024+1/16384) ~ 0.5/window). Resolved serially in lane
    //     order against CURRENT state — exact greedy order, because an accept0
    //     lane a > q cannot share q's row/col (q is an earlier valid lane),
    //     so committing accept0 first cannot change q's outcome.
    if (tid < 32) {
        int lane = tid;
        int assigned = 0;
        u64 key = (lane < (int)total) ? g_keys[lane] : 0ull;
        for (int base = 0; base < (int)total && assigned < NROWS; base += 32) {
            int nxt = base + 32 + lane;
            u64 key_next = (nxt < (int)total) ? __ldg(&g_keys[nxt]) : 0ull;

            int flat = 0xFFFFFF - (int)(key & 0xFFFFFFu);
            int r = flat >> 14;
            int c = flat & 0x3FFF;
            bool valid = (key != 0ull) && (rowUsed[r] == 0) && (colUsed[c] == 0);
            u32 validmask = __ballot_sync(0xFFFFFFFFu, valid);

            u32 rkey = valid ? (u32)r : (u32)(NROWS + lane);   // unique sentinels
            u32 ckey = valid ? (u32)c : (u32)(NCOLS + lane);
            u32 mR = __match_any_sync(0xFFFFFFFFu, rkey);
            u32 mC = __match_any_sync(0xFFFFFFFFu, ckey);
            u32 earlier = (1u << lane) - 1u;
            bool conflictE = (((mR | mC) & earlier & validmask) != 0u);
            bool acc0 = valid && !conflictE;
            u32 accmask = __ballot_sync(0xFFFFFFFFu, acc0);
            if (acc0) {
                rowUsed[r] = 1; colUsed[c] = 1;
                colOf[r] = (unsigned short)c;
            }
            assigned += __popc(accmask);
            __syncwarp();

            u32 quest = __ballot_sync(0xFFFFFFFFu, valid && conflictE);
            while (quest) {
                int q = __ffs(quest) - 1;
                quest &= quest - 1u;
                int qr = __shfl_sync(0xFFFFFFFFu, r, q);
                int qc = __shfl_sync(0xFFFFFFFFu, c, q);
                bool ok = (rowUsed[qr] == 0) && (colUsed[qc] == 0);
                if (ok) {
                    if (lane == 0) {
                        rowUsed[qr] = 1; colUsed[qc] = 1;
                        colOf[qr] = (unsigned short)qc;
                    }
                    assigned++;
                    __syncwarp();
                }
            }
            key = key_next;
        }
        if (lane == 0) scnt_s = assigned;
    }

    // ---- exact fallback: masked global argmax for any unassigned rows ----
    while (true) {
        __syncthreads();
        if (scnt_s >= NROWS) break;
        u64 best = 0;
        for (int i = tid; i < NTOT; i += 1024) {
            int r = i >> 14;
            if (rowUsed[r]) continue;
            int c = i & 0x3FFF;
            if (colUsed[c]) continue;
            float v = cost[i];
            u32 u = __float_as_uint(v);
            u32 enc = (u & 0x80000000u) ? ~u : (u | 0x80000000u);
            u64 kk = ((u64)enc << 24) | (u64)(0xFFFFFFu - (u32)i);
            if (kk > best) best = kk;
        }
        #pragma unroll
        for (int o = 16; o > 0; o >>= 1) {
            u64 t2 = __shfl_down_sync(0xFFFFFFFFu, best, o);
            if (t2 > best) best = t2;
        }
        if ((tid & 31) == 0) redBuf[tid >> 5] = best;
        __syncthreads();
        if (tid < 32) {
            u64 b = redBuf[tid];
            #pragma unroll
            for (int o = 16; o > 0; o >>= 1) {
                u64 t2 = __shfl_down_sync(0xFFFFFFFFu, b, o);
                if (t2 > b) b = t2;
            }
            if (tid == 0) {
                int flat = 0xFFFFFF - (int)(b & 0xFFFFFFu);
                int r = flat >> 14, c = flat & 0x3FFF;
                rowUsed[r] = 1; colUsed[c] = 1;
                colOf[r] = (unsigned short)c;
                scnt_s = scnt_s + 1;
            }
        }
        __syncthreads();
    }

    // ---- write output as float32: rows (arange) then cols ----
    if (out_size >= 2 * NROWS) {
        for (int i = tid; i < NROWS; i += 1024) {
            out[i] = (float)i;
            out[NROWS + i] = (float)colOf[i];
        }
    } else {
        for (int i = tid; i < NROWS && i < out_size; i += 1024)
            out[i] = (float)colOf[i];
    }
}

extern "C" void kernel_launch(void* const* d_in, const int* in_sizes, int n_in,
                              void* d_out, int out_size) {
    const float* cost = (const float*)d_in[0];
    float* out = (float*)d_out;
    (void)in_sizes; (void)n_in;

    k_init<<<8, 1024>>>();
    k_hist<<<SGRID, SBLK>>>((const float4*)cost);
    k_scan<<<1, 1024>>>();
    k_compact<<<SGRID, SBLK>>>((const float4*)cost);
    k_sortbins<<<FBINS, 128>>>();
    k_final<<<1, 1024>>>(cost, out, out_size);
}

// round 8
// speedup vs baseline: 3.6941x; 1.2482x over previous
#include <cuda_runtime.h>
#include <cstdint>

typedef unsigned long long u64;
typedef unsigned int u32;

#define NROWS 1024
#define NCOLS 16384
#define NTOT (NROWS*NCOLS)
#define CAP 32768
#define FBINS 4096
#define HLO 2.0f
#define HSCALE 1024.0f
#define BIN_MIN 1060      // value threshold ~= 2 + 1060/1024 = 3.035
#define BCAP 128          // slots per bin; expected ~65 at threshold density

#define SC_GRID 4096
#define SC_BLK 256
#define SC_STRIDE (SC_GRID*SC_BLK)   // 1048576; NTOT/4 = 4*SC_STRIDE exactly

// device-global scratch (no allocations allowed)
__device__ u32 g_bincnt[FBINS];
__device__ u32 g_binoff[FBINS];
__device__ u32 g_total;
__device__ u32 g_overflow;
__device__ u64 g_bucket[FBINS * BCAP];   // 4 MB
__device__ u64 g_keys[CAP];

__global__ void k_init() {
    int t = blockIdx.x * blockDim.x + threadIdx.x;
    int stride = gridDim.x * blockDim.x;
    for (int i = t; i < FBINS; i += stride) g_bincnt[i] = 0;
    if (t == 0) { g_total = 0; g_overflow = 0; }
}

__device__ __forceinline__ int binof(float v) {
    int b = (int)((v - HLO) * HSCALE);
    return (b > FBINS - 1) ? (FBINS - 1) : b;
}

// ONE full-matrix pass: scatter candidates (binof(v) >= BIN_MIN) into buckets
__global__ void __launch_bounds__(SC_BLK)
k_scatter(const float4* __restrict__ c4) {
    int idx = blockIdx.x * SC_BLK + threadIdx.x;
    float4 vv[4];
    #pragma unroll
    for (int k = 0; k < 4; k++) vv[k] = c4[idx + k * SC_STRIDE];   // MLP=4
    #pragma unroll
    for (int k = 0; k < 4; k++) {
        int i = idx + k * SC_STRIDE;
        float a[4] = { vv[k].x, vv[k].y, vv[k].z, vv[k].w };
        #pragma unroll
        for (int q = 0; q < 4; q++) {
            if (a[q] >= 3.0f) {                       // cheap pre-filter (< bin boundary)
                int b = binof(a[q]);
                if (b >= BIN_MIN) {
                    u32 pos = atomicAdd(&g_bincnt[b], 1u);
                    if (pos < BCAP) {
                        u32 flat = (u32)(i * 4 + q);
                        u32 enc = __float_as_uint(a[q]);  // candidates > 0: raw bits order-preserving
                        g_bucket[b * BCAP + pos] = ((u64)enc << 24) | (u64)(0xFFFFFFu - flat);
                    } else {
                        g_overflow = 1;
                    }
                }
            }
        }
    }
}

// one block: suffix-sum bucket counts (descending bins), offsets + total
__global__ void __launch_bounds__(1024)
k_scan() {
    __shared__ u32 s[1024];
    int tid = threadIdx.x;

    u32 x[4], pre[4];
    u32 run = 0;
    #pragma unroll
    for (int q = 0; q < 4; q++) {
        int b = FBINS - 1 - (tid * 4 + q);
        x[q] = g_bincnt[b];
        pre[q] = run;
        run += x[q];
    }
    s[tid] = run;
    __syncthreads();
    for (int off = 1; off < 1024; off <<= 1) {
        u32 t = (tid >= off) ? s[tid - off] : 0;
        __syncthreads();
        s[tid] += t;
        __syncthreads();
    }
    u32 excl = (tid > 0) ? s[tid - 1] : 0;

    #pragma unroll
    for (int q = 0; q < 4; q++) {
        int b = FBINS - 1 - (tid * 4 + q);
        u32 S = excl + pre[q] + x[q];      // inclusive suffix sum for bin b
        g_binoff[b] = S - x[q];            // start of bin b in descending concat
    }
    __syncthreads();
    if (tid == 1023) {
        u32 total = s[1023];
        if (total > CAP) { g_overflow = 1; total = 0; }
        g_total = total;
    }
}

// one block per bin: sort bucket desc (<=128 elems), emit into g_keys slice
__global__ void __launch_bounds__(128)
k_sortbins() {
    int b = blockIdx.x;
    u32 cnt = g_bincnt[b];
    if (cnt == 0) return;
    if (cnt > BCAP) return;          // overflow already flagged
    u32 off = g_binoff[b];
    int tid = threadIdx.x;
    if (cnt == 1) { if (tid == 0) g_keys[off] = g_bucket[b * BCAP]; return; }

    __shared__ u64 sk[128];
    u32 m = 2; while (m < cnt) m <<= 1;   // m <= 128
    if (tid < (int)m) sk[tid] = (tid < (int)cnt) ? g_bucket[b * BCAP + tid] : 0ull;
    __syncthreads();
    for (u32 k = 2; k <= m; k <<= 1) {
        for (u32 j = k >> 1; j > 0; j >>= 1) {
            if (tid < (int)m) {
                u32 p = tid ^ j;
                if (p > (u32)tid) {
                    u64 a = sk[tid], bb = sk[p];
                    bool desc = (((u32)tid & k) == 0);
                    if (desc ? (a < bb) : (a > bb)) { sk[tid] = bb; sk[p] = a; }
                }
            }
            __syncthreads();
        }
    }
    if (tid < (int)cnt) g_keys[off + tid] = sk[tid];
}

// greedy scan over globally-descending keys + exact fallback + output
__global__ void __launch_bounds__(1024, 1)
k_final(const float* __restrict__ cost, float* __restrict__ out, int out_size) {
    __shared__ unsigned char colUsed[NCOLS];
    __shared__ unsigned char rowUsed[NROWS];
    __shared__ unsigned short colOf[NROWS];
    __shared__ u64 redBuf[32];
    __shared__ int scnt_s;

    int tid = threadIdx.x;
    u32 total = g_total;
    if (g_overflow) total = 0;   // pathological: pure-fallback path (exact)

    for (int i = tid; i < NCOLS; i += 1024) colUsed[i] = 0;
    for (int i = tid; i < NROWS; i += 1024) { rowUsed[i] = 0; colOf[i] = 0; }
    if (tid == 0) scnt_s = 0;
    __syncthreads();

    // ---- warp-windowed greedy scan (warp 0), match-based parallel acceptance ----
    // accept0 lanes (valid, no conflict with earlier valid lane) are exactly
    // greedy-accepted and pairwise row/col-distinct -> parallel commit.
    // quest lanes (conflict with an earlier valid lane, ~0.5/window) resolve
    // serially in lane order against current state — exact greedy order.
    if (tid < 32) {
        int lane = tid;
        int assigned = 0;
        u64 key = (lane < (int)total) ? g_keys[lane] : 0ull;
        for (int base = 0; base < (int)total && assigned < NROWS; base += 32) {
            int nxt = base + 32 + lane;
            u64 key_next = (nxt < (int)total) ? __ldg(&g_keys[nxt]) : 0ull;

            int flat = 0xFFFFFF - (int)(key & 0xFFFFFFu);
            int r = flat >> 14;
            int c = flat & 0x3FFF;
            bool valid = (key != 0ull) && (rowUsed[r] == 0) && (colUsed[c] == 0);
            u32 validmask = __ballot_sync(0xFFFFFFFFu, valid);

            u32 rkey = valid ? (u32)r : (u32)(NROWS + lane);   // unique sentinels
            u32 ckey = valid ? (u32)c : (u32)(NCOLS + lane);
            u32 mR = __match_any_sync(0xFFFFFFFFu, rkey);
            u32 mC = __match_any_sync(0xFFFFFFFFu, ckey);
            u32 earlier = (1u << lane) - 1u;
            bool conflictE = (((mR | mC) & earlier & validmask) != 0u);
            bool acc0 = valid && !conflictE;
            u32 accmask = __ballot_sync(0xFFFFFFFFu, acc0);
            if (acc0) {
                rowUsed[r] = 1; colUsed[c] = 1;
                colOf[r] = (unsigned short)c;
            }
            assigned += __popc(accmask);
            __syncwarp();

            u32 quest = __ballot_sync(0xFFFFFFFFu, valid && conflictE);
            while (quest) {
                int q = __ffs(quest) - 1;
                quest &= quest - 1u;
                int qr = __shfl_sync(0xFFFFFFFFu, r, q);
                int qc = __shfl_sync(0xFFFFFFFFu, c, q);
                bool ok = (rowUsed[qr] == 0) && (colUsed[qc] == 0);
                if (ok) {
                    if (lane == 0) {
                        rowUsed[qr] = 1; colUsed[qc] = 1;
                        colOf[qr] = (unsigned short)qc;
                    }
                    assigned++;
                    __syncwarp();
                }
            }
            key = key_next;
        }
        if (lane == 0) scnt_s = assigned;
    }

    // ---- exact fallback: masked global argmax for any unassigned rows ----
    while (true) {
        __syncthreads();
        if (scnt_s >= NROWS) break;
        u64 best = 0;
        for (int i = tid; i < NTOT; i += 1024) {
            int r = i >> 14;
            if (rowUsed[r]) continue;
            int c = i & 0x3FFF;
            if (colUsed[c]) continue;
            float v = cost[i];
            u32 u = __float_as_uint(v);
            u32 enc = (u & 0x80000000u) ? ~u : (u | 0x80000000u);
            u64 kk = ((u64)enc << 24) | (u64)(0xFFFFFFu - (u32)i);
            if (kk > best) best = kk;
        }
        #pragma unroll
        for (int o = 16; o > 0; o >>= 1) {
            u64 t2 = __shfl_down_sync(0xFFFFFFFFu, best, o);
            if (t2 > best) best = t2;
        }
        if ((tid & 31) == 0) redBuf[tid >> 5] = best;
        __syncthreads();
        if (tid < 32) {
            u64 b = redBuf[tid];
            #pragma unroll
            for (int o = 16; o > 0; o >>= 1) {
                u64 t2 = __shfl_down_sync(0xFFFFFFFFu, b, o);
                if (t2 > b) b = t2;
            }
            if (tid == 0) {
                int flat = 0xFFFFFF - (int)(b & 0xFFFFFFu);
                int r = flat >> 14, c = flat & 0x3FFF;
                rowUsed[r] = 1; colUsed[c] = 1;
                colOf[r] = (unsigned short)c;
                scnt_s = scnt_s + 1;
            }
        }
        __syncthreads();
    }

    // ---- write output as float32: rows (arange) then cols ----
    if (out_size >= 2 * NROWS) {
        for (int i = tid; i < NROWS; i += 1024) {
            out[i] = (float)i;
            out[NROWS + i] = (float)colOf[i];
        }
    } else {
        for (int i = tid; i < NROWS && i < out_size; i += 1024)
            out[i] = (float)colOf[i];
    }
}

extern "C" void kernel_launch(void* const* d_in, const int* in_sizes, int n_in,
                              void* d_out, int out_size) {
    const float* cost = (const float*)d_in[0];
    float* out = (float*)d_out;
    (void)in_sizes; (void)n_in;

    k_init<<<8, 1024>>>();
    k_scatter<<<SC_GRID, SC_BLK>>>((const float4*)cost);
    k_scan<<<1, 1024>>>();
    k_sortbins<<<FBINS, 128>>>();
    k_final<<<1, 1024>>>(cost, out, out_size);
}

// round 9
// speedup vs baseline: 4.7059x; 1.2739x over previous
#include <cuda_runtime.h>
#include <cstdint>

typedef unsigned long long u64;
typedef unsigned int u32;

#define NROWS 1024
#define NCOLS 16384
#define NTOT (NROWS*NCOLS)
#define CAP 32768
#define FBINS 4096
#define HLO 2.0f
#define HSCALE 1024.0f
#define BIN_MIN 1060      // value threshold ~= 3.035
#define BCAP 128

#define SC_GRID 4096
#define SC_BLK 256
#define SC_STRIDE (SC_GRID*SC_BLK)   // NTOT/4 = 4*SC_STRIDE exactly

#define STAGE_KEYS 10240
#define STAGE_WINS (STAGE_KEYS/32)   // 320
#define FLAT_INVALID 0xFFFFFFFFu

// device-global scratch (no allocations allowed)
__device__ u32 g_bincnt[FBINS];
__device__ u32 g_binoff[FBINS];
__device__ u32 g_total;
__device__ u32 g_overflow;
__device__ u64 g_bucket[FBINS * BCAP];   // 4 MB
__device__ u64 g_keys[CAP];

__global__ void k_init() {
    int t = blockIdx.x * blockDim.x + threadIdx.x;
    int stride = gridDim.x * blockDim.x;
    for (int i = t; i < FBINS; i += stride) g_bincnt[i] = 0;
    if (t == 0) { g_total = 0; g_overflow = 0; }
}

__device__ __forceinline__ int binof(float v) {
    int b = (int)((v - HLO) * HSCALE);
    return (b > FBINS - 1) ? (FBINS - 1) : b;
}

// ONE full-matrix pass: scatter candidates (binof(v) >= BIN_MIN) into buckets
__global__ void __launch_bounds__(SC_BLK)
k_scatter(const float4* __restrict__ c4) {
    int idx = blockIdx.x * SC_BLK + threadIdx.x;
    float4 vv[4];
    #pragma unroll
    for (int k = 0; k < 4; k++) vv[k] = c4[idx + k * SC_STRIDE];   // MLP=4
    #pragma unroll
    for (int k = 0; k < 4; k++) {
        int i = idx + k * SC_STRIDE;
        float a[4] = { vv[k].x, vv[k].y, vv[k].z, vv[k].w };
        #pragma unroll
        for (int q = 0; q < 4; q++) {
            if (a[q] >= 3.0f) {
                int b = binof(a[q]);
                if (b >= BIN_MIN) {
                    u32 pos = atomicAdd(&g_bincnt[b], 1u);
                    if (pos < BCAP) {
                        u32 flat = (u32)(i * 4 + q);
                        u32 enc = __float_as_uint(a[q]);  // candidates > 0: bits order-preserving
                        g_bucket[b * BCAP + pos] = ((u64)enc << 24) | (u64)(0xFFFFFFu - flat);
                    } else {
                        g_overflow = 1;
                    }
                }
            }
        }
    }
}

// one block: suffix-sum bucket counts (descending bins), offsets + total
__global__ void __launch_bounds__(1024)
k_scan() {
    __shared__ u32 s[1024];
    int tid = threadIdx.x;

    u32 x[4], pre[4];
    u32 run = 0;
    #pragma unroll
    for (int q = 0; q < 4; q++) {
        int b = FBINS - 1 - (tid * 4 + q);
        x[q] = g_bincnt[b];
        pre[q] = run;
        run += x[q];
    }
    s[tid] = run;
    __syncthreads();
    for (int off = 1; off < 1024; off <<= 1) {
        u32 t = (tid >= off) ? s[tid - off] : 0;
        __syncthreads();
        s[tid] += t;
        __syncthreads();
    }
    u32 excl = (tid > 0) ? s[tid - 1] : 0;

    #pragma unroll
    for (int q = 0; q < 4; q++) {
        int b = FBINS - 1 - (tid * 4 + q);
        u32 S = excl + pre[q] + x[q];
        g_binoff[b] = S - x[q];
    }
    __syncthreads();
    if (tid == 1023) {
        u32 total = s[1023];
        if (total > CAP) { g_overflow = 1; total = 0; }
        g_total = total;
    }
}

// one block per bin: sort bucket desc (<=128 elems), emit into g_keys slice
__global__ void __launch_bounds__(128)
k_sortbins() {
    int b = blockIdx.x;
    u32 cnt = g_bincnt[b];
    if (cnt == 0) return;
    if (cnt > BCAP) return;          // overflow already flagged
    u32 off = g_binoff[b];
    int tid = threadIdx.x;
    if (cnt == 1) { if (tid == 0) g_keys[off] = g_bucket[b * BCAP]; return; }

    __shared__ u64 sk[128];
    u32 m = 2; while (m < cnt) m <<= 1;   // m <= 128
    if (tid < (int)m) sk[tid] = (tid < (int)cnt) ? g_bucket[b * BCAP + tid] : 0ull;
    __syncthreads();
    for (u32 k = 2; k <= m; k <<= 1) {
        for (u32 j = k >> 1; j > 0; j >>= 1) {
            if (tid < (int)m) {
                u32 p = tid ^ j;
                if (p > (u32)tid) {
                    u64 a = sk[tid], bb = sk[p];
                    bool desc = (((u32)tid & k) == 0);
                    if (desc ? (a < bb) : (a > bb)) { sk[tid] = bb; sk[p] = a; }
                }
            }
            __syncthreads();
        }
    }
    if (tid < (int)cnt) g_keys[off + tid] = sk[tid];
}

__device__ __forceinline__ bool bit_test(const u32* bits, int i) {
    return (bits[i >> 5] >> (i & 31)) & 1u;
}

// greedy scan over globally-descending keys + exact fallback + output
__global__ void __launch_bounds__(1024, 1)
k_final(const float* __restrict__ cost, float* __restrict__ out, int out_size) {
    __shared__ u32 sFlat[STAGE_KEYS];          // 40960 B
    __shared__ u32 sConf[STAGE_WINS];          // 1280 B
    __shared__ u32 colUsed[NCOLS / 32];        // 2048 B
    __shared__ u32 rowUsed[NROWS / 32];        // 128 B
    __shared__ unsigned short colOf[NROWS];    // 2048 B
    __shared__ u64 redBuf[32];
    __shared__ int scnt_s;

    int tid = threadIdx.x;
    int lane = tid & 31;
    int wid = tid >> 5;
    u32 total = g_total;
    if (g_overflow) total = 0;   // pathological: pure-fallback path (exact)

    for (int i = tid; i < NCOLS / 32; i += 1024) colUsed[i] = 0;
    for (int i = tid; i < NROWS / 32; i += 1024) rowUsed[i] = 0;
    for (int i = tid; i < NROWS; i += 1024) colOf[i] = 0;
    if (tid == 0) scnt_s = 0;

    // ---- stage first STAGE_KEYS flats into shared (all warps) ----
    for (int i = tid; i < STAGE_KEYS; i += 1024)
        sFlat[i] = (i < (int)total) ? (0xFFFFFFu - (u32)(g_keys[i] & 0xFFFFFFu))
                                    : FLAT_INVALID;
    __syncthreads();

    // ---- precompute per-window conflict masks (all warps in parallel) ----
    // conflict(lane) = shares row or col with ANY earlier lane in its window.
    for (int w = wid; w < STAGE_WINS; w += 32) {
        u32 flat = sFlat[w * 32 + lane];
        bool v = (flat != FLAT_INVALID);
        u32 rkey = v ? (flat >> 14) : (u32)(NROWS + lane);
        u32 ckey = v ? (flat & 0x3FFF) : (u32)(NCOLS + lane);
        u32 mR = __match_any_sync(0xFFFFFFFFu, rkey);
        u32 mC = __match_any_sync(0xFFFFFFFFu, ckey);
        u32 earlier = (1u << lane) - 1u;
        bool conf = (((mR | mC) & earlier) != 0u);
        u32 cm = __ballot_sync(0xFFFFFFFFu, conf);
        if (lane == 0) sConf[w] = cm;
    }
    __syncthreads();

    // ---- warp 0: greedy scan ----
    // accept0 = valid && no conflict with ANY earlier lane in window: exactly
    // greedy-accepted, pairwise row/col-distinct -> parallel commit.
    // quest lanes resolve serially in lane order vs current state (exact:
    // accept0 lanes share nothing with earlier lanes, so committing them
    // first cannot change a quest lane's outcome).
    if (wid == 0) {
        int assigned = 0;
        int base = 0;
        for (; base < (int)total && base < STAGE_KEYS && assigned < NROWS; base += 32) {
            u32 flat = sFlat[base + lane];
            u32 conf = sConf[base >> 5];
            int r = (int)(flat >> 14);
            int c = (int)(flat & 0x3FFF);
            bool valid = (flat != FLAT_INVALID) && !bit_test(rowUsed, r) && !bit_test(colUsed, c);
            bool myconf = (conf >> lane) & 1u;
            bool acc0 = valid && !myconf;
            u32 accmask = __ballot_sync(0xFFFFFFFFu, acc0);
            if (acc0) {
                atomicOr(&rowUsed[r >> 5], 1u << (r & 31));
                atomicOr(&colUsed[c >> 5], 1u << (c & 31));
                colOf[r] = (unsigned short)c;
            }
            assigned += __popc(accmask);
            __syncwarp();

            u32 quest = __ballot_sync(0xFFFFFFFFu, valid && myconf);
            while (quest) {
                int q = __ffs(quest) - 1;
                quest &= quest - 1u;
                int qr = __shfl_sync(0xFFFFFFFFu, r, q);
                int qc = __shfl_sync(0xFFFFFFFFu, c, q);
                bool ok = !bit_test(rowUsed, qr) && !bit_test(colUsed, qc);
                if (ok) {
                    if (lane == 0) {
                        atomicOr(&rowUsed[qr >> 5], 1u << (qr & 31));
                        atomicOr(&colUsed[qc >> 5], 1u << (qc & 31));
                        colOf[qr] = (unsigned short)qc;
                    }
                    assigned++;
                    __syncwarp();
                }
            }
        }
        // ---- legacy gmem tail (only if staged prefix exhausted) ----
        for (; base < (int)total && assigned < NROWS; base += 32) {
            int i = base + lane;
            u64 key = (i < (int)total) ? __ldg(&g_keys[i]) : 0ull;
            int flat = 0xFFFFFF - (int)(key & 0xFFFFFFu);
            int r = flat >> 14;
            int c = flat & 0x3FFF;
            bool valid = (key != 0ull) && !bit_test(rowUsed, r) && !bit_test(colUsed, c);
            u32 validmask = __ballot_sync(0xFFFFFFFFu, valid);
            u32 rkey = valid ? (u32)r : (u32)(NROWS + lane);
            u32 ckey = valid ? (u32)c : (u32)(NCOLS + lane);
            u32 mR = __match_any_sync(0xFFFFFFFFu, rkey);
            u32 mC = __match_any_sync(0xFFFFFFFFu, ckey);
            u32 earlier = (1u << lane) - 1u;
            bool conflictE = (((mR | mC) & earlier & validmask) != 0u);
            bool acc0 = valid && !conflictE;
            u32 accmask = __ballot_sync(0xFFFFFFFFu, acc0);
            if (acc0) {
                atomicOr(&rowUsed[r >> 5], 1u << (r & 31));
                atomicOr(&colUsed[c >> 5], 1u << (c & 31));
                colOf[r] = (unsigned short)c;
            }
            assigned += __popc(accmask);
            __syncwarp();
            u32 quest = __ballot_sync(0xFFFFFFFFu, valid && conflictE);
            while (quest) {
                int q = __ffs(quest) - 1;
                quest &= quest - 1u;
                int qr = __shfl_sync(0xFFFFFFFFu, r, q);
                int qc = __shfl_sync(0xFFFFFFFFu, c, q);
                bool ok = !bit_test(rowUsed, qr) && !bit_test(colUsed, qc);
                if (ok) {
                    if (lane == 0) {
                        atomicOr(&rowUsed[qr >> 5], 1u << (qr & 31));
                        atomicOr(&colUsed[qc >> 5], 1u << (qc & 31));
                        colOf[qr] = (unsigned short)qc;
                    }
                    assigned++;
                    __syncwarp();
                }
            }
        }
        if (lane == 0) scnt_s = assigned;
    }

    // ---- exact fallback: masked global argmax for any unassigned rows ----
    while (true) {
        __syncthreads();
        if (scnt_s >= NROWS) break;
        u64 best = 0;
        for (int i = tid; i < NTOT; i += 1024) {
            int r = i >> 14;
            if (bit_test(rowUsed, r)) continue;
            int c = i & 0x3FFF;
            if (bit_test(colUsed, c)) continue;
            float v = cost[i];
            u32 u = __float_as_uint(v);
            u32 enc = (u & 0x80000000u) ? ~u : (u | 0x80000000u);
            u64 kk = ((u64)enc << 24) | (u64)(0xFFFFFFu - (u32)i);
            if (kk > best) best = kk;
        }
        #pragma unroll
        for (int o = 16; o > 0; o >>= 1) {
            u64 t2 = __shfl_down_sync(0xFFFFFFFFu, best, o);
            if (t2 > best) best = t2;
        }
        if (lane == 0) redBuf[wid] = best;
        __syncthreads();
        if (tid < 32) {
            u64 b = redBuf[tid];
            #pragma unroll
            for (int o = 16; o > 0; o >>= 1) {
                u64 t2 = __shfl_down_sync(0xFFFFFFFFu, b, o);
                if (t2 > b) b = t2;
            }
            if (tid == 0) {
                int flat = 0xFFFFFF - (int)(b & 0xFFFFFFu);
                int r = flat >> 14, c = flat & 0x3FFF;
                rowUsed[r >> 5] |= 1u << (r & 31);
                colUsed[c >> 5] |= 1u << (c & 31);
                colOf[r] = (unsigned short)c;
                scnt_s = scnt_s + 1;
            }
        }
        __syncthreads();
    }

    // ---- write output as float32: rows (arange) then cols ----
    if (out_size >= 2 * NROWS) {
        for (int i = tid; i < NROWS; i += 1024) {
            out[i] = (float)i;
            out[NROWS + i] = (float)colOf[i];
        }
    } else {
        for (int i = tid; i < NROWS && i < out_size; i += 1024)
            out[i] = (float)colOf[i];
    }
}

extern "C" void kernel_launch(void* const* d_in, const int* in_sizes, int n_in,
                              void* d_out, int out_size) {
    const float* cost = (const float*)d_in[0];
    float* out = (float*)d_out;
    (void)in_sizes; (void)n_in;

    k_init<<<8, 1024>>>();
    k_scatter<<<SC_GRID, SC_BLK>>>((const float4*)cost);
    k_scan<<<1, 1024>>>();
    k_sortbins<<<FBINS, 128>>>();
    k_final<<<1, 1024>>>(cost, out, out_size);
}